// round 9
// baseline (speedup 1.0000x reference)
#include <cuda_runtime.h>
#include <cstdint>

// ROI max pool via 2D sparse tables (log-max), round 9.
//   ro = r >> 1; amin = max(a-ro,0); amax = a+ro; if (amax > LIM) amax = LIM-1;
//   bin i: [amin + (i*len)/8, amin + ((i+1)*len+7)/8)  -- width always in [1,6]
// fm: (C=256, H=64, W=64) f32. out: (N, C, 8, 8) f32.
//
// build_tables: TB[ky*3+kx][y][x][c] = max over fm[c][y..y+2^ky)[x..x+2^kx)
//   (edge-clamped; clamped entries never consumed). Channel-innermost.
//   R9: one y-row per CTA (512 CTAs), 4-row smem slab.
// roi_pool_main: warp = (cb, ph-half); lane = pwsub*8+cquad loads float4
//   (4 channels) per corner; 4 corners -> in-lane max. R9: occupancy capped
//   at 8 CTAs/SM via launch bounds (reg <= 64) to double resident warps.

namespace {
constexpr int Cdim  = 256;
constexpr int Hdim  = 64;
constexpr int Wdim  = 64;
constexpr int PLANE = Hdim * Wdim;              // 4096
constexpr int LVL   = PLANE * Cdim;             // floats per table level
constexpr int LVLB  = LVL * 4;                  // 4 MB per level
constexpr int YSTRB = Wdim * Cdim * 4;          // 65536
constexpr int XSTRB = Cdim * 4;                 // 1024
}

__device__ float TB[9 * LVL];                   // 36 MB scratch tables

// ---------------- table builder ----------------
// grid (8 c-chunks, 64 y-rows), block 256. Loads rows y..y+3 (clamped) into
// transposed smem S[row][x][c'], computes all 9 levels for 64 x-points.
__global__ __launch_bounds__(256)
void build_tables(const float* __restrict__ fm)
{
    const int c0 = blockIdx.x * 32;
    const int y0 = blockIdx.y;

    __shared__ float S[4][64][33];

    for (int idx = threadIdx.x; idx < 4 * 64 * 32; idx += 256) {
        const int row = idx >> 11;               // 0..3
        const int cc  = (idx >> 6) & 31;
        const int x   = idx & 63;
        int gy = y0 + row; if (gy > 63) gy = 63;
        S[row][x][cc] = fm[(size_t)(c0 + cc) * PLANE + gy * Wdim + x];
    }
    __syncthreads();

    const int lane = threadIdx.x & 31;
    const int warp = threadIdx.x >> 5;

    #pragma unroll
    for (int xi = 0; xi < 8; xi++) {
        const int x  = warp * 8 + xi;
        const int x1 = x + 1 > 63 ? 63 : x + 1;
        const int x2 = x + 2 > 63 ? 63 : x + 2;
        const int x3 = x + 3 > 63 ? 63 : x + 3;

        float v00 = S[0][x][lane], v01 = S[0][x1][lane],
              v02 = S[0][x2][lane], v03 = S[0][x3][lane];
        float v10 = S[1][x][lane], v11 = S[1][x1][lane],
              v12 = S[1][x2][lane], v13 = S[1][x3][lane];
        float v20 = S[2][x][lane], v21 = S[2][x1][lane],
              v22 = S[2][x2][lane], v23 = S[2][x3][lane];
        float v30 = S[3][x][lane], v31 = S[3][x1][lane],
              v32 = S[3][x2][lane], v33 = S[3][x3][lane];

        const float X1_0 = fmaxf(v00, v01), X2_0 = fmaxf(X1_0, fmaxf(v02, v03));
        const float X1_1 = fmaxf(v10, v11), X2_1 = fmaxf(X1_1, fmaxf(v12, v13));
        const float X1_2 = fmaxf(v20, v21), X2_2 = fmaxf(X1_2, fmaxf(v22, v23));
        const float X1_3 = fmaxf(v30, v31), X2_3 = fmaxf(X1_3, fmaxf(v32, v33));

        float t[9];
        t[0] = v00;                       // (ky0,kx0)
        t[1] = X1_0;                      // (ky0,kx1)
        t[2] = X2_0;                      // (ky0,kx2)
        t[3] = fmaxf(v00, v10);           // (ky1,kx0)
        t[4] = fmaxf(X1_0, X1_1);         // (ky1,kx1)
        t[5] = fmaxf(X2_0, X2_1);         // (ky1,kx2)
        t[6] = fmaxf(t[3], fmaxf(v20, v30));
        t[7] = fmaxf(t[4], fmaxf(X1_2, X1_3));
        t[8] = fmaxf(t[5], fmaxf(X2_2, X2_3));

        float* o = TB + ((size_t)y0 * Wdim + x) * Cdim + c0 + lane;
        #pragma unroll
        for (int i = 0; i < 9; i++) { *o = t[i]; o += LVL; }
    }
}

// ---------------- main kernel ----------------
// grid (4, N), block 128, min 8 blocks/SM (caps regs at 64 for occupancy).
__global__ __launch_bounds__(128, 8)
void roi_pool_main(const int4* __restrict__ rois, float* __restrict__ out)
{
    const int n    = blockIdx.y;
    const int warp = threadIdx.x >> 5;
    const int lane = threadIdx.x & 31;
    const int cb   = (blockIdx.x >> 1) * 4 + warp;   // 0..7
    const int phh  = blockIdx.x & 1;                 // ph half

    const int4 r = rois[n];
    const int yc = r.x, xc = r.y, rh = r.z, rw = r.w;
    const int roy = rh >> 1, rox = rw >> 1;

    int ymin = yc - roy; if (ymin < 0) ymin = 0;
    int ymax = yc + roy; if (ymax > Hdim) ymax = Hdim - 1;
    int xmin = xc - rox; if (xmin < 0) xmin = 0;
    int xmax = xc + rox; if (xmax > Wdim) xmax = Wdim - 1;

    const int leny = ymax - ymin;
    const int lenx = xmax - xmin;

    const int pwsub = lane >> 3;                 // 0..3
    const int cquad = lane & 7;                  // 0..7
    const int chb   = (cb * 32 + cquad * 4) * 4; // byte offset of lane's channels

    // x corner byte-offsets (incl. kx level term) for the two pw steps
    int xb0[2], xb1[2];
    #pragma unroll
    for (int s = 0; s < 2; s++) {
        const int pw = s * 4 + pwsub;
        const int cs = (pw * lenx) >> 3;
        const int ce = ((pw + 1) * lenx + 7) >> 3;
        const int rx = ce - cs;                            // 1..6
        const int kx = (rx >= 4) ? 2 : (rx >= 2 ? 1 : 0);  // 2^kx <= rx <= 2*2^kx
        xb0[s] = kx * LVLB + (xmin + cs) * XSTRB + chb;
        xb1[s] = kx * LVLB + (xmin + ce - (1 << kx)) * XSTRB + chb;
    }

    __shared__ float stage[4][16 * 36];
    float* st = stage[warp];

    const char* Bp = (const char*)TB;
    float* o = out + (size_t)n * (Cdim * 64) + cb * 32 * 64;

    #pragma unroll
    for (int php = 0; php < 2; php++) {          // two 16-bin chunks per warp
        #pragma unroll
        for (int ph2 = 0; ph2 < 2; ph2++) {
            const int ph = phh * 4 + php * 2 + ph2;
            const int rs = (ph * leny) >> 3;
            const int re = ((ph + 1) * leny + 7) >> 3;
            const int ry = re - rs;                            // 1..6
            const int ky = (ry >= 4) ? 2 : (ry >= 2 ? 1 : 0);
            const int ya0 = ky * 3 * LVLB + (ymin + rs) * YSTRB;
            const int ya1 = ky * 3 * LVLB + (ymin + re - (1 << ky)) * YSTRB;

            #pragma unroll
            for (int s = 0; s < 2; s++) {
                const float4 v00 = __ldg((const float4*)(Bp + ya0 + xb0[s]));
                const float4 v01 = __ldg((const float4*)(Bp + ya0 + xb1[s]));
                const float4 v10 = __ldg((const float4*)(Bp + ya1 + xb0[s]));
                const float4 v11 = __ldg((const float4*)(Bp + ya1 + xb1[s]));
                float4 m;
                m.x = fmaxf(fmaxf(v00.x, v01.x), fmaxf(v10.x, v11.x));
                m.y = fmaxf(fmaxf(v00.y, v01.y), fmaxf(v10.y, v11.y));
                m.z = fmaxf(fmaxf(v00.z, v01.z), fmaxf(v10.z, v11.z));
                m.w = fmaxf(fmaxf(v00.w, v01.w), fmaxf(v10.w, v11.w));

                const int bl = ph2 * 8 + s * 4 + pwsub;        // 0..15
                *(float4*)(st + bl * 36 + cquad * 4) = m;
            }
        }
        __syncwarp();

        // coalesced chunk writeback: 16 bins x 32 channels
        const int base = (phh * 2 + php) * 16;   // global bin offset of chunk
        #pragma unroll
        for (int i = 0; i < 16; i++) {
            const int g   = i * 32 + lane;
            const int cc  = g >> 4;              // channel within block (0..31)
            const int b16 = g & 15;              // bin within chunk
            o[cc * 64 + base + b16] = st[b16 * 36 + cc];
        }
        __syncwarp();                            // WAR before next chunk's stores
    }
}

extern "C" void kernel_launch(void* const* d_in, const int* in_sizes, int n_in,
                              void* d_out, int out_size)
{
    const float* fm   = (const float*)d_in[0];
    const int4*  rois = (const int4*)d_in[1];
    float*       out  = (float*)d_out;
    const int N = in_sizes[1] / 4;

    build_tables<<<dim3(8, 64), 256>>>(fm);
    roi_pool_main<<<dim3(4, N), 128>>>(rois, out);
}

// round 10
// speedup vs baseline: 1.0639x; 1.0639x over previous
#include <cuda_runtime.h>
#include <cstdint>

// ROI max pool via 2D sparse tables (log-max), round 10.
//   ro = r >> 1; amin = max(a-ro,0); amax = a+ro; if (amax > LIM) amax = LIM-1;
//   bin i: [amin + (i*len)/8, amin + ((i+1)*len+7)/8)  -- width always in [1,6]
// fm: (C=256, H=64, W=64) f32. out: (N, C, 8, 8) f32.
//
// Tables: TB[ky*3+kx][y][x][c] = max over fm[c][y..y+2^ky)[x..x+2^kx) (clamped;
// clamped entries never consumed). Channel-innermost -> coalesced everywhere.
// Build = 3 streaming passes:
//   build_x: transpose + x-levels (ky=0, kx=0..2), grid(8,64), no redundancy.
//   pool_y (x2): T[ky+1 tier] = max(T[src][y], T[src][min(y+dy,63)]); one
//     float4 per thread, fully coalesced (y-pooling is free in this layout).
// Main (= R8, 17.95us): warp=(cb,ph-half); lane=pwsub*8+cquad loads float4
//   (4 channels) per corner; 4 corners -> in-lane max; smem-staged coalesced out.

namespace {
constexpr int Cdim  = 256;
constexpr int Hdim  = 64;
constexpr int Wdim  = 64;
constexpr int PLANE = Hdim * Wdim;              // 4096
constexpr int LVL   = PLANE * Cdim;             // floats per table level
constexpr int LVL4  = LVL / 4;                  // float4s per level = 262144
constexpr int LVLB  = LVL * 4;                  // 4 MB per level
constexpr int YSTRB = Wdim * Cdim * 4;          // 65536
constexpr int XSTRB = Cdim * 4;                 // 1024
}

__device__ float TB[9 * LVL];                   // 36 MB scratch tables

// ---------------- pass 1: transpose + x-levels ----------------
// grid (8 c-chunks, 64 y-rows), block 256.
__global__ __launch_bounds__(256)
void build_x(const float* __restrict__ fm)
{
    const int c0 = blockIdx.x * 32;
    const int y0 = blockIdx.y;

    __shared__ float S[64][33];

    for (int idx = threadIdx.x; idx < 64 * 32; idx += 256) {
        const int cc = idx >> 6;
        const int x  = idx & 63;
        S[x][cc] = fm[(size_t)(c0 + cc) * PLANE + y0 * Wdim + x];
    }
    __syncthreads();

    const int lane = threadIdx.x & 31;
    const int warp = threadIdx.x >> 5;

    #pragma unroll
    for (int xi = 0; xi < 8; xi++) {
        const int x  = warp * 8 + xi;
        const int x1 = x + 1 > 63 ? 63 : x + 1;
        const int x2 = x + 2 > 63 ? 63 : x + 2;
        const int x3 = x + 3 > 63 ? 63 : x + 3;

        const float v0 = S[x][lane], v1 = S[x1][lane],
                    v2 = S[x2][lane], v3 = S[x3][lane];
        const float X1 = fmaxf(v0, v1);
        const float X2 = fmaxf(X1, fmaxf(v2, v3));

        float* o = TB + ((size_t)y0 * Wdim + x) * Cdim + c0 + lane;
        o[0]           = v0;   // (ky0,kx0)
        o[LVL]         = X1;   // (ky0,kx1)
        o[2 * (size_t)LVL] = X2;   // (ky0,kx2)
    }
}

// ---------------- pass 2/3: y-pooling (streaming, coalesced) ----------------
// One float4 (4 channels) per thread. 3 levels x 4096 positions x 64 = 786432.
// dst[lvl][y][x][:] = max(src[lvl][y][x][:], src[lvl][min(y+dy,63)][x][:]).
__global__ __launch_bounds__(256)
void pool_y(int srcb, int dstb, int dy)
{
    const int t   = blockIdx.x * 256 + threadIdx.x;
    const int lvl = t >> 18;            // / 262144
    const int rem = t & 262143;
    const int pos = rem >> 6;           // y*64 + x
    const int c4  = rem & 63;
    const int y   = pos >> 6;
    const int x   = pos & 63;
    int yc = y + dy; if (yc > 63) yc = 63;

    const float4* src = (const float4*)TB + (size_t)(srcb + lvl) * LVL4;
    float4*       dst = (float4*)TB       + (size_t)(dstb + lvl) * LVL4;

    const float4 a = src[rem];
    const float4 b = src[((yc << 6) + x) * 64 + c4];
    float4 m;
    m.x = fmaxf(a.x, b.x);
    m.y = fmaxf(a.y, b.y);
    m.z = fmaxf(a.z, b.z);
    m.w = fmaxf(a.w, b.w);
    dst[rem] = m;
}

// ---------------- main kernel (R8 config) ----------------
// grid (4, N), block 128. bx: cb-group = bx>>1, ph-half = bx&1.
__global__ __launch_bounds__(128)
void roi_pool_main(const int4* __restrict__ rois, float* __restrict__ out)
{
    const int n    = blockIdx.y;
    const int warp = threadIdx.x >> 5;
    const int lane = threadIdx.x & 31;
    const int cb   = (blockIdx.x >> 1) * 4 + warp;   // 0..7
    const int phh  = blockIdx.x & 1;                 // ph half

    const int4 r = rois[n];
    const int yc = r.x, xc = r.y, rh = r.z, rw = r.w;
    const int roy = rh >> 1, rox = rw >> 1;

    int ymin = yc - roy; if (ymin < 0) ymin = 0;
    int ymax = yc + roy; if (ymax > Hdim) ymax = Hdim - 1;
    int xmin = xc - rox; if (xmin < 0) xmin = 0;
    int xmax = xc + rox; if (xmax > Wdim) xmax = Wdim - 1;

    const int leny = ymax - ymin;
    const int lenx = xmax - xmin;

    const int pwsub = lane >> 3;                 // 0..3
    const int cquad = lane & 7;                  // 0..7
    const int chb   = (cb * 32 + cquad * 4) * 4; // byte offset of lane's channels

    // x corner byte-offsets (incl. kx level term) for the two pw steps
    int xb0[2], xb1[2];
    #pragma unroll
    for (int s = 0; s < 2; s++) {
        const int pw = s * 4 + pwsub;
        const int cs = (pw * lenx) >> 3;
        const int ce = ((pw + 1) * lenx + 7) >> 3;
        const int rx = ce - cs;                            // 1..6
        const int kx = (rx >= 4) ? 2 : (rx >= 2 ? 1 : 0);  // 2^kx <= rx <= 2*2^kx
        xb0[s] = kx * LVLB + (xmin + cs) * XSTRB + chb;
        xb1[s] = kx * LVLB + (xmin + ce - (1 << kx)) * XSTRB + chb;
    }

    __shared__ float stage[4][16 * 36];
    float* st = stage[warp];

    const char* Bp = (const char*)TB;
    float* o = out + (size_t)n * (Cdim * 64) + cb * 32 * 64;

    #pragma unroll
    for (int php = 0; php < 2; php++) {          // two 16-bin chunks per warp
        #pragma unroll
        for (int ph2 = 0; ph2 < 2; ph2++) {
            const int ph = phh * 4 + php * 2 + ph2;
            const int rs = (ph * leny) >> 3;
            const int re = ((ph + 1) * leny + 7) >> 3;
            const int ry = re - rs;                            // 1..6
            const int ky = (ry >= 4) ? 2 : (ry >= 2 ? 1 : 0);
            const int ya0 = ky * 3 * LVLB + (ymin + rs) * YSTRB;
            const int ya1 = ky * 3 * LVLB + (ymin + re - (1 << ky)) * YSTRB;

            #pragma unroll
            for (int s = 0; s < 2; s++) {
                const float4 v00 = __ldg((const float4*)(Bp + ya0 + xb0[s]));
                const float4 v01 = __ldg((const float4*)(Bp + ya0 + xb1[s]));
                const float4 v10 = __ldg((const float4*)(Bp + ya1 + xb0[s]));
                const float4 v11 = __ldg((const float4*)(Bp + ya1 + xb1[s]));
                float4 m;
                m.x = fmaxf(fmaxf(v00.x, v01.x), fmaxf(v10.x, v11.x));
                m.y = fmaxf(fmaxf(v00.y, v01.y), fmaxf(v10.y, v11.y));
                m.z = fmaxf(fmaxf(v00.z, v01.z), fmaxf(v10.z, v11.z));
                m.w = fmaxf(fmaxf(v00.w, v01.w), fmaxf(v10.w, v11.w));

                const int bl = ph2 * 8 + s * 4 + pwsub;        // 0..15
                *(float4*)(st + bl * 36 + cquad * 4) = m;
            }
        }
        __syncwarp();

        // coalesced chunk writeback: 16 bins x 32 channels
        const int base = (phh * 2 + php) * 16;   // global bin offset of chunk
        #pragma unroll
        for (int i = 0; i < 16; i++) {
            const int g   = i * 32 + lane;
            const int cc  = g >> 4;              // channel within block (0..31)
            const int b16 = g & 15;              // bin within chunk
            o[cc * 64 + base + b16] = st[b16 * 36 + cc];
        }
        __syncwarp();                            // WAR before next chunk's stores
    }
}

extern "C" void kernel_launch(void* const* d_in, const int* in_sizes, int n_in,
                              void* d_out, int out_size)
{
    const float* fm   = (const float*)d_in[0];
    const int4*  rois = (const int4*)d_in[1];
    float*       out  = (float*)d_out;
    const int N = in_sizes[1] / 4;

    build_x<<<dim3(8, 64), 256>>>(fm);
    pool_y<<<3072, 256>>>(0, 3, 1);   // ky=1 tier from ky=0
    pool_y<<<3072, 256>>>(3, 6, 2);   // ky=2 tier from ky=1
    roi_pool_main<<<dim3(4, N), 128>>>(rois, out);
}

// round 13
// speedup vs baseline: 1.0874x; 1.0221x over previous
#include <cuda_runtime.h>
#include <cstdint>

// ROI max pool via 2D sparse tables (log-max), round 11.
//   ro = r >> 1; amin = max(a-ro,0); amax = a+ro; if (amax > LIM) amax = LIM-1;
//   bin i: [amin + (i*len)/8, amin + ((i+1)*len+7)/8)  -- width always in [1,6]
// fm: (C=256, H=64, W=64) f32. out: (N, C, 8, 8) f32.
//
// Tables: TB[ky*3+kx][y][x][c] = max over fm[c][y..y+2^ky)[x..x+2^kx) (edge-
// clamped; clamped entries never consumed). Channel-innermost layout.
// Build = 2 passes:
//   build_x: transpose + x-levels (ky=0, kx=0..2), grid(8,64), no redundancy.
//   pool_y_both: ONE pass computes both y-tiers straight from ky0:
//     T1[y] = max(row y, row y+1), T2[y] = max(rows y..y+3)  (rows clamped).
//     One float4 (4 channels) per thread, 4 loads / 2 stores, fully coalesced.
// Main (= R8, ~17.2us, 80 regs): warp=(cb,ph-half); lane=pwsub*8+cquad loads
//   float4 (4 channels) per corner; 4 corners -> in-lane max; smem-staged
//   coalesced output.

namespace {
constexpr int Cdim  = 256;
constexpr int Hdim  = 64;
constexpr int Wdim  = 64;
constexpr int PLANE = Hdim * Wdim;              // 4096
constexpr int LVL   = PLANE * Cdim;             // floats per table level
constexpr int LVL4  = LVL / 4;                  // float4s per level = 262144
constexpr int LVLB  = LVL * 4;                  // 4 MB per level
constexpr int YSTRB = Wdim * Cdim * 4;          // 65536
constexpr int XSTRB = Cdim * 4;                 // 1024
}

__device__ float TB[9 * LVL];                   // 36 MB scratch tables

// ---------------- pass 1: transpose + x-levels ----------------
// grid (8 c-chunks, 64 y-rows), block 256.
__global__ __launch_bounds__(256)
void build_x(const float* __restrict__ fm)
{
    const int c0 = blockIdx.x * 32;
    const int y0 = blockIdx.y;

    __shared__ float S[64][33];

    for (int idx = threadIdx.x; idx < 64 * 32; idx += 256) {
        const int cc = idx >> 6;
        const int x  = idx & 63;
        S[x][cc] = fm[(size_t)(c0 + cc) * PLANE + y0 * Wdim + x];
    }
    __syncthreads();

    const int lane = threadIdx.x & 31;
    const int warp = threadIdx.x >> 5;

    #pragma unroll
    for (int xi = 0; xi < 8; xi++) {
        const int x  = warp * 8 + xi;
        const int x1 = x + 1 > 63 ? 63 : x + 1;
        const int x2 = x + 2 > 63 ? 63 : x + 2;
        const int x3 = x + 3 > 63 ? 63 : x + 3;

        const float v0 = S[x][lane], v1 = S[x1][lane],
                    v2 = S[x2][lane], v3 = S[x3][lane];
        const float X1 = fmaxf(v0, v1);
        const float X2 = fmaxf(X1, fmaxf(v2, v3));

        float* o = TB + ((size_t)y0 * Wdim + x) * Cdim + c0 + lane;
        o[0]               = v0;   // (ky0,kx0)
        o[LVL]             = X1;   // (ky0,kx1)
        o[2 * (size_t)LVL] = X2;   // (ky0,kx2)
    }
}

// ---------------- pass 2: both y-tiers in one streaming pass ----------------
// One float4 (4 channels) per thread; 3 levels x 4096 pos x 64 = 786432 threads.
// Loads ky0 rows y..y+3 (clamped), writes ky1 = max(2 rows), ky2 = max(4 rows).
__global__ __launch_bounds__(256)
void pool_y_both()
{
    const int t   = blockIdx.x * 256 + threadIdx.x;
    const int lvl = t >> 18;            // / 262144 -> 0..2
    const int rem = t & 262143;
    const int pos = rem >> 6;           // y*64 + x
    const int c4  = rem & 63;
    const int y   = pos >> 6;
    const int x   = pos & 63;
    const int y1  = y + 1 > 63 ? 63 : y + 1;
    const int y2  = y + 2 > 63 ? 63 : y + 2;
    const int y3  = y + 3 > 63 ? 63 : y + 3;

    const float4* src = (const float4*)TB + (size_t)lvl * LVL4;
    const float4 a = src[rem];
    const float4 b = src[((y1 << 6) + x) * 64 + c4];
    const float4 c = src[((y2 << 6) + x) * 64 + c4];
    const float4 d = src[((y3 << 6) + x) * 64 + c4];

    float4 t1, t2;
    t1.x = fmaxf(a.x, b.x); t1.y = fmaxf(a.y, b.y);
    t1.z = fmaxf(a.z, b.z); t1.w = fmaxf(a.w, b.w);
    t2.x = fmaxf(t1.x, fmaxf(c.x, d.x)); t2.y = fmaxf(t1.y, fmaxf(c.y, d.y));
    t2.z = fmaxf(t1.z, fmaxf(c.z, d.z)); t2.w = fmaxf(t1.w, fmaxf(c.w, d.w));

    ((float4*)TB)[(size_t)(3 + lvl) * LVL4 + rem] = t1;
    ((float4*)TB)[(size_t)(6 + lvl) * LVL4 + rem] = t2;
}

// ---------------- main kernel (R8 config, frozen) ----------------
// grid (4, N), block 128. bx: cb-group = bx>>1, ph-half = bx&1.
__global__ __launch_bounds__(128)
void roi_pool_main(const int4* __restrict__ rois, float* __restrict__ out)
{
    const int n    = blockIdx.y;
    const int warp = threadIdx.x >> 5;
    const int lane = threadIdx.x & 31;
    const int cb   = (blockIdx.x >> 1) * 4 + warp;   // 0..7
    const int phh  = blockIdx.x & 1;                 // ph half

    const int4 r = rois[n];
    const int yc = r.x, xc = r.y, rh = r.z, rw = r.w;
    const int roy = rh >> 1, rox = rw >> 1;

    int ymin = yc - roy; if (ymin < 0) ymin = 0;
    int ymax = yc + roy; if (ymax > Hdim) ymax = Hdim - 1;
    int xmin = xc - rox; if (xmin < 0) xmin = 0;
    int xmax = xc + rox; if (xmax > Wdim) xmax = Wdim - 1;

    const int leny = ymax - ymin;
    const int lenx = xmax - xmin;

    const int pwsub = lane >> 3;                 // 0..3
    const int cquad = lane & 7;                  // 0..7
    const int chb   = (cb * 32 + cquad * 4) * 4; // byte offset of lane's channels

    // x corner byte-offsets (incl. kx level term) for the two pw steps
    int xb0[2], xb1[2];
    #pragma unroll
    for (int s = 0; s < 2; s++) {
        const int pw = s * 4 + pwsub;
        const int cs = (pw * lenx) >> 3;
        const int ce = ((pw + 1) * lenx + 7) >> 3;
        const int rx = ce - cs;                            // 1..6
        const int kx = (rx >= 4) ? 2 : (rx >= 2 ? 1 : 0);  // 2^kx <= rx <= 2*2^kx
        xb0[s] = kx * LVLB + (xmin + cs) * XSTRB + chb;
        xb1[s] = kx * LVLB + (xmin + ce - (1 << kx)) * XSTRB + chb;
    }

    __shared__ float stage[4][16 * 36];
    float* st = stage[warp];

    const char* Bp = (const char*)TB;
    float* o = out + (size_t)n * (Cdim * 64) + cb * 32 * 64;

    #pragma unroll
    for (int php = 0; php < 2; php++) {          // two 16-bin chunks per warp
        #pragma unroll
        for (int ph2 = 0; ph2 < 2; ph2++) {
            const int ph = phh * 4 + php * 2 + ph2;
            const int rs = (ph * leny) >> 3;
            const int re = ((ph + 1) * leny + 7) >> 3;
            const int ry = re - rs;                            // 1..6
            const int ky = (ry >= 4) ? 2 : (ry >= 2 ? 1 : 0);
            const int ya0 = ky * 3 * LVLB + (ymin + rs) * YSTRB;
            const int ya1 = ky * 3 * LVLB + (ymin + re - (1 << ky)) * YSTRB;

            #pragma unroll
            for (int s = 0; s < 2; s++) {
                const float4 v00 = __ldg((const float4*)(Bp + ya0 + xb0[s]));
                const float4 v01 = __ldg((const float4*)(Bp + ya0 + xb1[s]));
                const float4 v10 = __ldg((const float4*)(Bp + ya1 + xb0[s]));
                const float4 v11 = __ldg((const float4*)(Bp + ya1 + xb1[s]));
                float4 m;
                m.x = fmaxf(fmaxf(v00.x, v01.x), fmaxf(v10.x, v11.x));
                m.y = fmaxf(fmaxf(v00.y, v01.y), fmaxf(v10.y, v11.y));
                m.z = fmaxf(fmaxf(v00.z, v01.z), fmaxf(v10.z, v11.z));
                m.w = fmaxf(fmaxf(v00.w, v01.w), fmaxf(v10.w, v11.w));

                const int bl = ph2 * 8 + s * 4 + pwsub;        // 0..15
                *(float4*)(st + bl * 36 + cquad * 4) = m;
            }
        }
        __syncwarp();

        // coalesced chunk writeback: 16 bins x 32 channels
        const int base = (phh * 2 + php) * 16;   // global bin offset of chunk
        #pragma unroll
        for (int i = 0; i < 16; i++) {
            const int g   = i * 32 + lane;
            const int cc  = g >> 4;              // channel within block (0..31)
            const int b16 = g & 15;              // bin within chunk
            o[cc * 64 + base + b16] = st[b16 * 36 + cc];
        }
        __syncwarp();                            // WAR before next chunk's stores
    }
}

extern "C" void kernel_launch(void* const* d_in, const int* in_sizes, int n_in,
                              void* d_out, int out_size)
{
    const float* fm   = (const float*)d_in[0];
    const int4*  rois = (const int4*)d_in[1];
    float*       out  = (float*)d_out;
    const int N = in_sizes[1] / 4;

    build_x<<<dim3(8, 64), 256>>>(fm);
    pool_y_both<<<3072, 256>>>();
    roi_pool_main<<<dim3(4, N), 128>>>(rois, out);
}